// round 14
// baseline (speedup 1.0000x reference)
#include <cuda_runtime.h>
#include <cuda_fp16.h>

// Shape fixed by setup_inputs: B=32, S=2048, E=NQ=4.
#define NB 32
#define NS 2048
#define NROWS (NB * NS)   // 65536
#define CHUNK_G4 16       // 16 uint4 rows = 64 key-groups = 512 keys per chunk
#define ATHREADS 128      // 4 warps -> 1024 blocks -> ~7 blocks/SM

// MMA fragment-layout scratch (__device__ globals, zero-init; pad words never stored).
__device__ unsigned g_qf[NB * 128 * 32 * 2];   // Q A-frags
__device__ unsigned g_kf[NB * 64 * 32 * 4];    // K B-frags
__device__ unsigned g_vf[NB * 64 * 32 * 4];    // V' B-frags (half2 words)

// Collapsed circuit: partial products of cos(x_q + w_q).
__device__ __forceinline__ float4 circuit4(float4 x, const float* w) {
    float u0 = __cosf(x.x + w[0]);
    float u1 = __cosf(x.y + w[1]);
    float u2 = __cosf(x.z + w[2]);
    float u3 = __cosf(x.w + w[3]);
    float4 r;
    r.y = u0 * u1;
    r.z = r.y * u2;
    r.w = r.z * u3;
    r.x = u1 * u2 * u3;
    return r;
}

__device__ __forceinline__ unsigned packh2(float lo, float hi) {
    __half2 h = __floats2half2_rn(lo, hi);
    return *reinterpret_cast<unsigned*>(&h);
}

// Role-split QKV: blocks 0-255 -> Q frags, 256-511 -> K frags, 512-767 -> V' frags.
__global__ void __launch_bounds__(256) qkv_kernel(
    const float* __restrict__ x,
    const float* __restrict__ wQ,
    const float* __restrict__ wK,
    const float* __restrict__ wV)
{
    unsigned t = blockIdx.x * 256 + threadIdx.x;
    unsigned role = t >> 16;
    unsigned n = t & (NROWS - 1);
    int b = n >> 11, kl = n & 2047;
    float4 xv = reinterpret_cast<const float4*>(x)[n];

    if (role == 0) {
        const float ALPHA = 0.72134752044448170367f;  // 0.5 * log2(e)
        float4 q = circuit4(xv, wQ);
        int qg = kl >> 4, r = kl & 15;
        int j = r >> 3, rb = r & 7;
        unsigned base = (((b * 128 + qg) * 32) + rb * 4) * 2 + j;
        g_qf[base]     = packh2(q.x * ALPHA, q.y * ALPHA);
        g_qf[base + 2] = packh2(q.z * ALPHA, q.w * ALPHA);
        // k-dim pad words stay statically zero.
    } else if (role == 1) {
        float4 k = circuit4(xv, wK);
        int g = kl >> 3, s = kl & 7;
        int g4 = g >> 2, j = g & 3;
        unsigned base = ((((b * 64 + g4) * 32) + s * 4) * 4) + j;
        g_kf[base]     = packh2(k.x, k.y);
        g_kf[base + 4] = packh2(k.z, k.w);
        // pad rows 4-7 stay statically zero.
    } else {
        float4 v = circuit4(xv, wV);
        float vals[5] = {v.x, v.y, v.z, v.w, 1.0f};
        float pv[5];
        #pragma unroll
        for (int c = 0; c < 5; c++)
            pv[c] = __shfl_xor_sync(0xFFFFFFFFu, vals[c], 1);
        if ((kl & 1) == 0) {
            int g = kl >> 3, s = kl & 7;
            int g4 = g >> 2, j = g & 3, sp = s >> 1;
            unsigned rowbase = (b * 64 + g4) * 32;
            #pragma unroll
            for (int c = 0; c < 5; c++)
                g_vf[(rowbase + c * 4 + sp) * 4 + j] = packh2(vals[c], pv[c]);
            // cols 5-7 stay statically zero.
        }
    }
}

// 16-key step: 2x QK m16n8k8 (f16 out) -> ex2 -> 1x PV m16n8k16 (f32 acc).
__device__ __forceinline__ void step16(uint2 aq, unsigned k0, unsigned k1,
                                       unsigned v0, unsigned v1,
                                       float& d0, float& d1, float& d2, float& d3)
{
    unsigned p0, p1, p2, p3;
    asm("mma.sync.aligned.m16n8k8.row.col.f16.f16.f16.f16 "
        "{%0,%1}, {%2,%3}, {%4}, {%5,%6};"
        : "=r"(p0), "=r"(p1)
        : "r"(aq.x), "r"(aq.y), "r"(k0), "r"(0u), "r"(0u));
    asm("mma.sync.aligned.m16n8k8.row.col.f16.f16.f16.f16 "
        "{%0,%1}, {%2,%3}, {%4}, {%5,%6};"
        : "=r"(p2), "=r"(p3)
        : "r"(aq.x), "r"(aq.y), "r"(k1), "r"(0u), "r"(0u));
    asm("ex2.approx.f16x2 %0, %0;" : "+r"(p0));
    asm("ex2.approx.f16x2 %0, %0;" : "+r"(p1));
    asm("ex2.approx.f16x2 %0, %0;" : "+r"(p2));
    asm("ex2.approx.f16x2 %0, %0;" : "+r"(p3));
    asm("mma.sync.aligned.m16n8k16.row.col.f32.f16.f16.f32 "
        "{%0,%1,%2,%3}, {%4,%5,%6,%7}, {%8,%9}, {%0,%1,%2,%3};"
        : "+f"(d0), "+f"(d1), "+f"(d2), "+f"(d3)
        : "r"(p0), "r"(p1), "r"(p2), "r"(p3), "r"(v0), "r"(v1));
}

__global__ void __launch_bounds__(ATHREADS) attn_kernel(
    const float* __restrict__ wC, float* __restrict__ out)
{
    __shared__ uint4 sK[CHUNK_G4 * 32];   // 8 KB
    __shared__ uint4 sV[CHUNK_G4 * 32];   // 8 KB
    __shared__ float epi[4][16][6];

    int b = blockIdx.y;
    int w = threadIdx.x >> 5, lane = threadIdx.x & 31;
    int qg = blockIdx.x * 4 + w;

    uint2 aq = reinterpret_cast<const uint2*>(g_qf)[(b * 128 + qg) * 32 + lane];

    // Dual accumulator sets: halves the PV HMMA RAW chain.
    float d0 = 0.f, d1 = 0.f, d2 = 0.f, d3 = 0.f;
    float e0 = 0.f, e1 = 0.f, e2 = 0.f, e3 = 0.f;

    for (int c = 0; c < 4; c++) {   // 4 chunks of 512 keys
        int g4base = (b * 64) + c * CHUNK_G4;
        __syncthreads();
        const uint4* gk = reinterpret_cast<const uint4*>(g_kf) + g4base * 32;
        const uint4* gv = reinterpret_cast<const uint4*>(g_vf) + g4base * 32;
        #pragma unroll
        for (int i = 0; i < 4; i++) {
            sK[threadIdx.x + i * ATHREADS] = gk[threadIdx.x + i * ATHREADS];
            sV[threadIdx.x + i * ATHREADS] = gv[threadIdx.x + i * ATHREADS];
        }
        __syncthreads();
        #pragma unroll 4
        for (int g4 = 0; g4 < CHUNK_G4; g4++) {
            uint4 kk = sK[g4 * 32 + lane];
            uint4 vv = sV[g4 * 32 + lane];
            step16(aq, kk.x, kk.y, vv.x, vv.y, d0, d1, d2, d3);
            step16(aq, kk.z, kk.w, vv.z, vv.w, e0, e1, e2, e3);
        }
    }
    d0 += e0; d1 += e1; d2 += e2; d3 += e3;

    // Epilogue: PV C cols per lane%4: 0->(v0,v1) 1->(v2,v3) 2->(den,0) 3->(0,0)
    int r = lane >> 2, q4 = lane & 3;
    if (q4 == 0) {
        epi[w][r][0] = d0; epi[w][r][1] = d1;
        epi[w][r + 8][0] = d2; epi[w][r + 8][1] = d3;
    } else if (q4 == 1) {
        epi[w][r][2] = d0; epi[w][r][3] = d1;
        epi[w][r + 8][2] = d2; epi[w][r + 8][3] = d3;
    } else if (q4 == 2) {
        epi[w][r][4] = d0;
        epi[w][r + 8][4] = d2;
    }
    __syncwarp();
    if (lane < 16) {
        float inv = 1.0f / epi[w][lane][4];
        float4 ctx = make_float4(epi[w][lane][0] * inv, epi[w][lane][1] * inv,
                                 epi[w][lane][2] * inv, epi[w][lane][3] * inv);
        int n = b * NS + qg * 16 + lane;
        reinterpret_cast<float4*>(out)[n] = circuit4(ctx, wC);
    }
}

extern "C" void kernel_launch(void* const* d_in, const int* in_sizes, int n_in,
                              void* d_out, int out_size)
{
    const float* x  = (const float*)d_in[0];
    const float* wQ = (const float*)d_in[1];
    const float* wK = (const float*)d_in[2];
    const float* wV = (const float*)d_in[3];
    const float* wC = (const float*)d_in[4];
    float* out = (float*)d_out;

    qkv_kernel<<<3 * NROWS / 256, 256>>>(x, wQ, wK, wV);
    attn_kernel<<<dim3(32, NB), ATHREADS>>>(wC, out);
}

// round 15
// speedup vs baseline: 1.4730x; 1.4730x over previous
#include <cuda_runtime.h>
#include <cuda_fp16.h>

// Shape fixed by setup_inputs: B=32, S=2048, E=NQ=4.
#define NB 32
#define NS 2048
#define NROWS (NB * NS)   // 65536
#define KSPLIT 2
#define CHUNK_G4 16       // 16 uint4 rows = 64 key-groups = 512 keys per chunk

// MMA fragment-layout scratch (__device__ globals, zero-init).
__device__ unsigned g_qf[NB * 128 * 32 * 2];   // Q A-frags
__device__ unsigned g_kf[NB * 64 * 32 * 4];    // K B-frags
__device__ unsigned g_vf[NB * 64 * 32 * 4];    // V' B-frags (half2 words)
// Split-K partials.
__device__ float4 g_pv[KSPLIT * NROWS];
__device__ float  g_pd[KSPLIT * NROWS];

// Collapsed circuit: partial products of cos(x_q + w_q).
__device__ __forceinline__ float4 circuit4(float4 x, const float* w) {
    float u0 = __cosf(x.x + w[0]);
    float u1 = __cosf(x.y + w[1]);
    float u2 = __cosf(x.z + w[2]);
    float u3 = __cosf(x.w + w[3]);
    float4 r;
    r.y = u0 * u1;
    r.z = r.y * u2;
    r.w = r.z * u3;
    r.x = u1 * u2 * u3;
    return r;
}

__device__ __forceinline__ unsigned packh2(float lo, float hi) {
    __half2 h = __floats2half2_rn(lo, hi);
    return *reinterpret_cast<unsigned*>(&h);
}

// Role-split QKV with SMEM-STAGED COALESCED stores.
// Each block covers 256 contiguous rows -> exactly 1024 fragment words (4KB)
// at gmem word base blk*1024 for its role array. Scatter into zeroed smem
// (pads come free), then 256 coalesced uint4 stores.
__global__ void __launch_bounds__(256) qkv_kernel(
    const float* __restrict__ x,
    const float* __restrict__ wQ,
    const float* __restrict__ wK,
    const float* __restrict__ wV)
{
    __shared__ unsigned st[1024];

    unsigned role = blockIdx.x >> 8;
    unsigned blk  = blockIdx.x & 255;
    int tid = threadIdx.x;
    int n = blk * 256 + tid;          // global row
    int kl = n & 2047;                // row within batch

    // Zero the staging tile (covers all pad words).
    reinterpret_cast<uint4*>(st)[tid] = make_uint4(0, 0, 0, 0);
    float4 xv = reinterpret_cast<const float4*>(x)[n];
    __syncthreads();

    unsigned* dst;
    if (role == 0) {
        const float ALPHA = 0.72134752044448170367f;  // 0.5 * log2(e)
        float4 q = circuit4(xv, wQ);
        int lqg = (kl >> 4) & 15;     // local 16-query group (16 per block)
        int r = kl & 15;
        int j = r >> 3, rb = r & 7;
        unsigned base = (lqg * 32 + rb * 4) * 2 + j;
        st[base]     = packh2(q.x * ALPHA, q.y * ALPHA);
        st[base + 2] = packh2(q.z * ALPHA, q.w * ALPHA);
        dst = g_qf + blk * 1024;
    } else if (role == 1) {
        float4 k = circuit4(xv, wK);
        int g = kl >> 3, s = kl & 7;
        int lg4 = (g >> 2) & 7;       // local g4 (8 per block)
        int j = g & 3;
        unsigned base = (lg4 * 32 + s * 4) * 4 + j;
        st[base]     = packh2(k.x, k.y);
        st[base + 4] = packh2(k.z, k.w);
        dst = g_kf + blk * 1024;
    } else {
        float4 v = circuit4(xv, wV);
        float vals[5] = {v.x, v.y, v.z, v.w, 1.0f};
        float pv[5];
        #pragma unroll
        for (int c = 0; c < 5; c++)
            pv[c] = __shfl_xor_sync(0xFFFFFFFFu, vals[c], 1);
        if ((kl & 1) == 0) {
            int g = kl >> 3, s = kl & 7;
            int lg4 = (g >> 2) & 7;
            int j = g & 3, sp = s >> 1;
            #pragma unroll
            for (int c = 0; c < 5; c++)
                st[(lg4 * 32 + c * 4 + sp) * 4 + j] = packh2(vals[c], pv[c]);
        }
        dst = g_vf + blk * 1024;
    }
    __syncthreads();
    // Coalesced writeback: 1024 words = 256 uint4.
    reinterpret_cast<uint4*>(dst)[tid] =
        reinterpret_cast<const uint4*>(st)[tid];
}

// 16-key step: 2x QK m16n8k8 (f16 out) -> ex2 -> 1x PV m16n8k16 (f32 acc).
__device__ __forceinline__ void step16(uint2 aq, unsigned k0, unsigned k1,
                                       unsigned v0, unsigned v1,
                                       float& d0, float& d1, float& d2, float& d3)
{
    unsigned p0, p1, p2, p3;
    asm("mma.sync.aligned.m16n8k8.row.col.f16.f16.f16.f16 "
        "{%0,%1}, {%2,%3}, {%4}, {%5,%6};"
        : "=r"(p0), "=r"(p1)
        : "r"(aq.x), "r"(aq.y), "r"(k0), "r"(0u), "r"(0u));
    asm("mma.sync.aligned.m16n8k8.row.col.f16.f16.f16.f16 "
        "{%0,%1}, {%2,%3}, {%4}, {%5,%6};"
        : "=r"(p2), "=r"(p3)
        : "r"(aq.x), "r"(aq.y), "r"(k1), "r"(0u), "r"(0u));
    asm("ex2.approx.f16x2 %0, %0;" : "+r"(p0));
    asm("ex2.approx.f16x2 %0, %0;" : "+r"(p1));
    asm("ex2.approx.f16x2 %0, %0;" : "+r"(p2));
    asm("ex2.approx.f16x2 %0, %0;" : "+r"(p3));
    asm("mma.sync.aligned.m16n8k16.row.col.f32.f16.f16.f32 "
        "{%0,%1,%2,%3}, {%4,%5,%6,%7}, {%8,%9}, {%0,%1,%2,%3};"
        : "+f"(d0), "+f"(d1), "+f"(d2), "+f"(d3)
        : "r"(p0), "r"(p1), "r"(p2), "r"(p3), "r"(v0), "r"(v1));
}

__global__ void __launch_bounds__(256) attn_kernel()
{
    __shared__ uint4 sK[CHUNK_G4 * 32];   // 8 KB
    __shared__ uint4 sV[CHUNK_G4 * 32];   // 8 KB
    __shared__ float epi[8][16][6];

    int b = blockIdx.y;
    int split = blockIdx.z;
    int w = threadIdx.x >> 5, lane = threadIdx.x & 31;
    int qg = blockIdx.x * 8 + w;

    uint2 aq = reinterpret_cast<const uint2*>(g_qf)[(b * 128 + qg) * 32 + lane];

    float d0 = 0.f, d1 = 0.f, d2 = 0.f, d3 = 0.f;

    for (int c = 0; c < 2; c++) {   // 2 chunks of 512 keys per split
        int g4base = (b * 64) + split * 32 + c * CHUNK_G4;
        __syncthreads();
        const uint4* gk = reinterpret_cast<const uint4*>(g_kf) + g4base * 32;
        const uint4* gv = reinterpret_cast<const uint4*>(g_vf) + g4base * 32;
        sK[threadIdx.x]       = gk[threadIdx.x];
        sK[threadIdx.x + 256] = gk[threadIdx.x + 256];
        sV[threadIdx.x]       = gv[threadIdx.x];
        sV[threadIdx.x + 256] = gv[threadIdx.x + 256];
        __syncthreads();
        #pragma unroll 4
        for (int g4 = 0; g4 < CHUNK_G4; g4++) {
            uint4 kk = sK[g4 * 32 + lane];
            uint4 vv = sV[g4 * 32 + lane];
            step16(aq, kk.x, kk.y, vv.x, vv.y, d0, d1, d2, d3);
            step16(aq, kk.z, kk.w, vv.z, vv.w, d0, d1, d2, d3);
        }
    }

    // Epilogue: PV C cols per lane%4: 0->(v0,v1) 1->(v2,v3) 2->(den,0) 3->(0,0)
    int r = lane >> 2, q4 = lane & 3;
    if (q4 == 0) {
        epi[w][r][0] = d0; epi[w][r][1] = d1;
        epi[w][r + 8][0] = d2; epi[w][r + 8][1] = d3;
    } else if (q4 == 1) {
        epi[w][r][2] = d0; epi[w][r][3] = d1;
        epi[w][r + 8][2] = d2; epi[w][r + 8][3] = d3;
    } else if (q4 == 2) {
        epi[w][r][4] = d0;
        epi[w][r + 8][4] = d2;
    }
    __syncwarp();
    if (lane < 16) {
        int n = b * NS + qg * 16 + lane;
        g_pv[split * NROWS + n] = make_float4(epi[w][lane][0], epi[w][lane][1],
                                              epi[w][lane][2], epi[w][lane][3]);
        g_pd[split * NROWS + n] = epi[w][lane][4];
    }
}

__global__ void __launch_bounds__(256) combine_kernel(
    const float* __restrict__ wC, float* __restrict__ out)
{
    int n = blockIdx.x * 256 + threadIdx.x;
    float4 a = g_pv[n];
    float4 c = g_pv[NROWS + n];
    float den = g_pd[n] + g_pd[NROWS + n];
    float inv = 1.0f / den;
    float4 ctx = make_float4((a.x + c.x) * inv, (a.y + c.y) * inv,
                             (a.z + c.z) * inv, (a.w + c.w) * inv);
    reinterpret_cast<float4*>(out)[n] = circuit4(ctx, wC);
}

extern "C" void kernel_launch(void* const* d_in, const int* in_sizes, int n_in,
                              void* d_out, int out_size)
{
    const float* x  = (const float*)d_in[0];
    const float* wQ = (const float*)d_in[1];
    const float* wK = (const float*)d_in[2];
    const float* wV = (const float*)d_in[3];
    const float* wC = (const float*)d_in[4];
    float* out = (float*)d_out;

    qkv_kernel<<<3 * 256, 256>>>(x, wQ, wK, wV);
    attn_kernel<<<dim3(16, NB, KSPLIT), 256>>>();
    combine_kernel<<<NROWS / 256, 256>>>(wC, out);
}